// round 7
// baseline (speedup 1.0000x reference)
#include <cuda_runtime.h>
#include <cuda_fp16.h>
#include <cstdint>

#define NMAX 50000
#define EMAX 800000
#define H 128
#define NBLK 592          // 4 blocks/SM on 148 SMs -> always co-resident
#define GSZ (NBLK * 256)
#define NWARPS (NBLK * 8)

// ---------------- scratch (__device__ globals) ------------------------------
__device__ float4 g_aggr[NMAX * (H / 4)];  // segment-sum of nb rows (fp32)
__device__ uint2  g_nbh[NMAX * 32];        // node_embedding as fp16 (256B/row)
__device__ float  g_s[NMAX];               // per-node sum of edge_attr
__device__ float4 g_v3[H / 4];             // relu(W4) @ W3
__device__ int    g_cnt[NMAX];             // degree counts -> fill cursors
__device__ int    g_off[NMAX + 1];         // CSR row offsets
__device__ int    g_bsum[64];              // per-chunk sums for scan (49 used)
__device__ int    g_cols[EMAX];            // CSR column indices

// grid barrier state (self-resetting across graph replays)
__device__ unsigned g_bar_count = 0;
__device__ unsigned g_bar_sense = 0;

// ---------------------------------------------------------------------------
__device__ __forceinline__ unsigned long long pack2(float v) {
    unsigned long long r;
    asm("mov.b64 %0, {%1, %1};" : "=l"(r) : "f"(v));
    return r;
}
__device__ __forceinline__ void unpack2(unsigned long long p, float& lo, float& hi) {
    asm("mov.b64 {%0, %1}, %2;" : "=f"(lo), "=f"(hi) : "l"(p));
}
__device__ __forceinline__ void ffma2(unsigned long long& d,
                                      unsigned long long a,
                                      unsigned long long b) {
    asm("fma.rn.f32x2 %0, %1, %2, %0;" : "+l"(d) : "l"(a), "l"(b));
}

// sense-reversing grid barrier; lsense lives in thread 0's registers
__device__ __forceinline__ void grid_bar(unsigned& lsense) {
    __syncthreads();
    if (threadIdx.x == 0) {
        lsense ^= 1u;
        __threadfence();
        unsigned old = atomicAdd(&g_bar_count, 1u);
        if (old == NBLK - 1u) {
            g_bar_count = 0u;
            __threadfence();
            atomicExch(&g_bar_sense, lsense);
        } else {
            while (*(volatile unsigned*)&g_bar_sense != lsense) __nanosleep(32);
        }
        __threadfence();
    }
    __syncthreads();
}

// ---------------------------------------------------------------------------
// Mega kernel: prep | hist | scan1 | scan3 | fill | aggr, barrier-separated.
// ---------------------------------------------------------------------------
__global__ void __launch_bounds__(256, 4)
mega_kernel(const void* __restrict__ ei, const float* __restrict__ ea,
            const float* __restrict__ nb, const float* __restrict__ W4,
            const float* __restrict__ W3, int n, int e, int n4, int nbs) {
    __shared__ int s_bs[64];
    __shared__ int s_ts[256];

    const int t    = threadIdx.x;
    const int gtid = blockIdx.x * 256 + t;
    unsigned lsense = 0;
    if (t == 0) lsense = *(volatile unsigned*)&g_bar_sense;

    const int* p32 = (const int*)ei;
    const bool is64 = (p32[1] | p32[3] | p32[5] | p32[7]) == 0;
    const long long* p64 = (const long long*)ei;

    // ---- P0: zero cnt/s, fp16 convert, v3 ----------------------------------
    for (int i = gtid; i < n * 32; i += GSZ) {
        float4 v = ((const float4*)nb)[i];
        __half2 h0 = __floats2half2_rn(v.x, v.y);
        __half2 h1 = __floats2half2_rn(v.z, v.w);
        uint2 u;
        u.x = *(unsigned*)&h0;
        u.y = *(unsigned*)&h1;
        g_nbh[i] = u;
    }
    for (int i = gtid; i < n; i += GSZ) { g_cnt[i] = 0; g_s[i] = 0.f; }
    if (blockIdx.x == 0 && t < H) {
        float acc = 0.f;
#pragma unroll 8
        for (int c = 0; c < H; ++c) {
            float w = W4[c];
            w = w > 0.f ? w : 0.f;
            acc += w * W3[c * H + t];
        }
        ((float*)g_v3)[t] = acc;
    }
    grid_bar(lsense);

    // ---- P1: histogram + edge-attr sums ------------------------------------
    for (int i = gtid; i < e; i += GSZ) {
        int r = is64 ? (int)p64[i] : p32[i];
        if ((unsigned)r < (unsigned)n) {
            atomicAdd(&g_cnt[r], 1);
            atomicAdd(&g_s[r], ea[i]);
        }
    }
    grid_bar(lsense);

    // ---- P2: per-chunk sums (chunk = 1024 counts) --------------------------
    if ((int)blockIdx.x < nbs) {
        int i = blockIdx.x * 256 + t;
        int4 v = (i < n4) ? ((const int4*)g_cnt)[i] : make_int4(0, 0, 0, 0);
        int s = v.x + v.y + v.z + v.w;
#pragma unroll
        for (int o = 16; o > 0; o >>= 1) s += __shfl_down_sync(0xffffffffu, s, o);
        if ((t & 31) == 0) s_ts[t >> 5] = s;
        __syncthreads();
        if (t == 0) {
            int a = 0;
#pragma unroll
            for (int k = 0; k < 8; ++k) a += s_ts[k];
            g_bsum[blockIdx.x] = a;
        }
    }
    grid_bar(lsense);

    // ---- P3: offsets (scan chunk sums + local scan) ------------------------
    if ((int)blockIdx.x < nbs) {
        int i = blockIdx.x * 256 + t;
        if (t < 64) s_bs[t] = (t < nbs) ? g_bsum[t] : 0;
        __syncthreads();
#pragma unroll
        for (int d = 1; d < 64; d <<= 1) {
            int v = (t < 64 && t >= d) ? s_bs[t - d] : 0;
            __syncthreads();
            if (t < 64) s_bs[t] += v;
            __syncthreads();
        }
        int base  = (blockIdx.x == 0) ? 0 : s_bs[blockIdx.x - 1];
        int total = s_bs[nbs - 1];

        int4 v = (i < n4) ? ((const int4*)g_cnt)[i] : make_int4(0, 0, 0, 0);
        int tot = v.x + v.y + v.z + v.w;
        s_ts[t] = tot;
        __syncthreads();
#pragma unroll
        for (int d = 1; d < 256; d <<= 1) {
            int xv = (t >= d) ? s_ts[t - d] : 0;
            __syncthreads();
            s_ts[t] += xv;
            __syncthreads();
        }
        if (i < n4) {
            int o0 = base + s_ts[t] - tot;
            int o1 = o0 + v.x, o2 = o1 + v.y, o3 = o2 + v.z;
            int4 offs = make_int4(o0, o1, o2, o3);
            ((int4*)g_off)[i] = offs;
            ((int4*)g_cnt)[i] = offs;   // fill cursors
        }
        if (blockIdx.x == 0 && t == 0) g_off[n] = total;
    }
    grid_bar(lsense);

    // ---- P4: CSR fill ------------------------------------------------------
    for (int i = gtid; i < e; i += GSZ) {
        int r, c;
        if (is64) { r = (int)p64[i]; c = (int)p64[e + i]; }
        else      { r = p32[i];      c = p32[e + i]; }
        if ((unsigned)r >= (unsigned)n || (unsigned)c >= (unsigned)n) continue;
        int pos = atomicAdd(&g_cnt[r], 1);
        g_cols[pos] = c;
    }
    grid_bar(lsense);

    // ---- P5: aggregate (warp per row, fp16 gathers, fp32 accumulate) -------
    const int lane = t & 31;
    for (int w = gtid >> 5; w < n; w += NWARPS) {
        int beg = g_off[w], end = g_off[w + 1];
        float4 acc = make_float4(0.f, 0.f, 0.f, 0.f);
        int j = beg;
        for (; j + 4 <= end; j += 4) {
            int c0 = g_cols[j], c1 = g_cols[j + 1];
            int c2 = g_cols[j + 2], c3 = g_cols[j + 3];
            uint2 u0 = g_nbh[c0 * 32 + lane];
            uint2 u1 = g_nbh[c1 * 32 + lane];
            uint2 u2 = g_nbh[c2 * 32 + lane];
            uint2 u3 = g_nbh[c3 * 32 + lane];
#pragma unroll
            for (int q = 0; q < 4; ++q) {
                uint2 u = (q == 0) ? u0 : (q == 1) ? u1 : (q == 2) ? u2 : u3;
                float2 a = __half22float2(*(__half2*)&u.x);
                float2 b = __half22float2(*(__half2*)&u.y);
                acc.x += a.x; acc.y += a.y; acc.z += b.x; acc.w += b.y;
            }
        }
        for (; j < end; ++j) {
            int c = g_cols[j];
            uint2 u = g_nbh[c * 32 + lane];
            float2 a = __half22float2(*(__half2*)&u.x);
            float2 b = __half22float2(*(__half2*)&u.y);
            acc.x += a.x; acc.y += a.y; acc.z += b.x; acc.w += b.y;
        }
        g_aggr[w * 32 + lane] = acc;
    }
}

// ---------------------------------------------------------------------------
// Fused GEMM + epilogue:  out = relu( x@W1 + aggr@W2 + s*v3 )
// 256 thr, 64 rows x 128 cols, FFMA2 mainloop (A pre-packed row pairs).
// ---------------------------------------------------------------------------
__global__ void gemm_fused_kernel(const float* __restrict__ x,
                                  const float* __restrict__ W1,
                                  const float* __restrict__ W2,
                                  float* __restrict__ out, int n) {
    extern __shared__ float sm[];
    float* Bs = sm;            // [128][128] = W2
    float* As = sm + H * H;    // [128][64]  = aggr tile (k-major)
    const int t = threadIdx.x;
    const int rbase = blockIdx.x * 64;

    for (int i = t; i < H * H / 4; i += 256)
        ((float4*)Bs)[i] = ((const float4*)W2)[i];

    for (int i = t; i < 64 * 32; i += 256) {
        int row = i >> 5;
        int kq  = i & 31;
        int r = rbase + row;
        float4 v = (r < n) ? g_aggr[r * 32 + kq]
                           : make_float4(0.f, 0.f, 0.f, 0.f);
        As[(4 * kq + 0) * 64 + row] = v.x;
        As[(4 * kq + 1) * 64 + row] = v.y;
        As[(4 * kq + 2) * 64 + row] = v.z;
        As[(4 * kq + 3) * 64 + row] = v.w;
    }
    __syncthreads();

    const int lane = t & 31;
    const int wid  = t >> 5;
    const int r0   = wid * 8;
    const int c0   = lane * 4;

    unsigned long long accp[4][4];
#pragma unroll
    for (int rp = 0; rp < 4; ++rp)
#pragma unroll
        for (int c = 0; c < 4; ++c) accp[rp][c] = 0ULL;

#pragma unroll 4
    for (int k = 0; k < H; ++k) {
        const float4 b = *(const float4*)&Bs[k * H + c0];
        unsigned long long bp[4] = {pack2(b.x), pack2(b.y), pack2(b.z), pack2(b.w)};
        const unsigned long long* ap =
            (const unsigned long long*)&As[k * 64 + r0];
        unsigned long long a0 = ap[0], a1 = ap[1], a2 = ap[2], a3 = ap[3];
#pragma unroll
        for (int c = 0; c < 4; ++c) {
            ffma2(accp[0][c], a0, bp[c]);
            ffma2(accp[1][c], a1, bp[c]);
            ffma2(accp[2][c], a2, bp[c]);
            ffma2(accp[3][c], a3, bp[c]);
        }
    }

    float4 v3v = g_v3[lane];
#pragma unroll
    for (int rp = 0; rp < 4; ++rp) {
        float lo[4], hi[4];
#pragma unroll
        for (int c = 0; c < 4; ++c) unpack2(accp[rp][c], lo[c], hi[c]);
#pragma unroll
        for (int half = 0; half < 2; ++half) {
            int r = rbase + r0 + 2 * rp + half;
            if (r >= n) continue;
            float4 o;
            if (half == 0) { o.x = lo[0]; o.y = lo[1]; o.z = lo[2]; o.w = lo[3]; }
            else           { o.x = hi[0]; o.y = hi[1]; o.z = hi[2]; o.w = hi[3]; }
            float s = g_s[r];
            o.x += s * v3v.x; o.y += s * v3v.y; o.z += s * v3v.z; o.w += s * v3v.w;

            float4 xv0 = ((const float4*)x)[r * 2];
            float4 xv1 = ((const float4*)x)[r * 2 + 1];
            float xk[8] = {xv0.x, xv0.y, xv0.z, xv0.w, xv1.x, xv1.y, xv1.z, xv1.w};
#pragma unroll
            for (int k = 0; k < 8; ++k) {
                float4 wv = ((const float4*)W1)[k * 32 + lane];
                o.x += xk[k] * wv.x;
                o.y += xk[k] * wv.y;
                o.z += xk[k] * wv.z;
                o.w += xk[k] * wv.w;
            }
            o.x = o.x > 0.f ? o.x : 0.f;
            o.y = o.y > 0.f ? o.y : 0.f;
            o.z = o.z > 0.f ? o.z : 0.f;
            o.w = o.w > 0.f ? o.w : 0.f;
            ((float4*)out)[r * 32 + lane] = o;
        }
    }
}

// ---------------------------------------------------------------------------
extern "C" void kernel_launch(void* const* d_in, const int* in_sizes, int n_in,
                              void* d_out, int out_size) {
    const float* x   = (const float*)d_in[0];
    const void*  ei  = d_in[1];                 // int32 or int64 (device-detected)
    const float* ea  = (const float*)d_in[2];
    const float* nb  = (const float*)d_in[3];
    const float* W1  = (const float*)d_in[4];
    const float* W2  = (const float*)d_in[5];
    const float* W3  = (const float*)d_in[6];
    const float* W4  = (const float*)d_in[7];
    float* out = (float*)d_out;

    const int n   = in_sizes[0] / 8;   // 50000
    const int e   = in_sizes[2];       // 800000
    const int n4  = (n + 3) / 4;       // 12500
    const int nbs = (n4 + 255) / 256;  // 49 scan chunks

    const int smem = (H * H + H * 64) * sizeof(float);  // 98304 B
    cudaFuncSetAttribute(gemm_fused_kernel,
                         cudaFuncAttributeMaxDynamicSharedMemorySize, smem);

    mega_kernel<<<NBLK, 256>>>(ei, ea, nb, W4, W3, n, e, n4, nbs);
    gemm_fused_kernel<<<(n + 63) / 64, 256, smem>>>(x, W1, W2, out, n);
}

// round 8
// speedup vs baseline: 1.0823x; 1.0823x over previous
#include <cuda_runtime.h>
#include <cuda_fp16.h>
#include <cstdint>

#define NMAX 50000
#define EMAX 800000
#define H 128
#define GEMM_BLOCKS 296   // 2 per SM on 148 SMs

// ---------------- scratch (__device__ globals) ------------------------------
__device__ float4 g_aggr[NMAX * (H / 4)];  // segment-sum of nb rows (fp32)
__device__ uint2  g_nbh[NMAX * 32];        // node_embedding as fp16 (256B/row)
__device__ float  g_s[NMAX];               // per-node sum of edge_attr
__device__ float4 g_v3[H / 4];             // relu(W4) @ W3
__device__ int    g_cnt[NMAX];             // degree counts -> fill cursors
__device__ int    g_off[NMAX + 1];         // CSR row offsets
__device__ int    g_bsum[64];              // per-chunk sums for scan (49 used)
__device__ int    g_cols[EMAX];            // CSR column indices

// ---------------------------------------------------------------------------
__device__ __forceinline__ unsigned long long pack2(float v) {
    unsigned long long r;
    asm("mov.b64 %0, {%1, %1};" : "=l"(r) : "f"(v));
    return r;
}
__device__ __forceinline__ void unpack2(unsigned long long p, float& lo, float& hi) {
    asm("mov.b64 {%0, %1}, %2;" : "=f"(lo), "=f"(hi) : "l"(p));
}
__device__ __forceinline__ void ffma2(unsigned long long& d,
                                      unsigned long long a,
                                      unsigned long long b) {
    asm("fma.rn.f32x2 %0, %1, %2, %0;" : "+l"(d) : "l"(a), "l"(b));
}

__device__ __forceinline__ void load_edge(const void* __restrict__ ei, int e,
                                          int idx, int& r, int& c) {
    const int* p32 = (const int*)ei;
    bool is64 = (p32[1] | p32[3] | p32[5] | p32[7]) == 0;  // int64 => odd words 0
    if (is64) {
        const long long* p64 = (const long long*)ei;
        r = (int)p64[idx];
        c = (int)p64[e + idx];
    } else {
        r = p32[idx];
        c = p32[e + idx];
    }
}

// ---------------------------------------------------------------------------
// Prep: zero cnt/s, convert nb -> fp16 table, v3 = relu(W4)@W3 (block 0).
// ---------------------------------------------------------------------------
__global__ void prep_kernel(const float* __restrict__ nb,
                            const float* __restrict__ W4,
                            const float* __restrict__ W3, int n) {
    int i = blockIdx.x * blockDim.x + threadIdx.x;
    if (i < n) { g_cnt[i] = 0; g_s[i] = 0.f; }
    if (i < n * 32) {
        float4 v = ((const float4*)nb)[i];
        __half2 h0 = __floats2half2_rn(v.x, v.y);
        __half2 h1 = __floats2half2_rn(v.z, v.w);
        uint2 u;
        u.x = *(unsigned*)&h0;
        u.y = *(unsigned*)&h1;
        g_nbh[i] = u;
    }
    if (blockIdx.x == 0 && threadIdx.x < H) {
        int j = threadIdx.x;
        float acc = 0.f;
#pragma unroll 8
        for (int c = 0; c < H; ++c) {
            float w = W4[c];
            w = w > 0.f ? w : 0.f;
            acc += w * W3[c * H + j];
        }
        ((float*)g_v3)[j] = acc;
    }
}

// ---------------------------------------------------------------------------
__global__ void hist_kernel(const void* __restrict__ ei,
                            const float* __restrict__ ea, int e, int n) {
    int i = blockIdx.x * blockDim.x + threadIdx.x;
    if (i >= e) return;
    int r, c;
    load_edge(ei, e, i, r, c);
    if ((unsigned)r < (unsigned)n) {
        atomicAdd(&g_cnt[r], 1);
        atomicAdd(&g_s[r], ea[i]);
    }
}

// ---------------------------------------------------------------------------
__global__ void scan1_kernel(int n4) {
    __shared__ int ws[8];
    int t = threadIdx.x;
    int i = blockIdx.x * 256 + t;
    int4 v = (i < n4) ? ((const int4*)g_cnt)[i] : make_int4(0, 0, 0, 0);
    int s = v.x + v.y + v.z + v.w;
#pragma unroll
    for (int o = 16; o > 0; o >>= 1) s += __shfl_down_sync(0xffffffffu, s, o);
    if ((t & 31) == 0) ws[t >> 5] = s;
    __syncthreads();
    if (t == 0) {
        int a = 0;
#pragma unroll
        for (int k = 0; k < 8; ++k) a += ws[k];
        g_bsum[blockIdx.x] = a;
    }
}

// ---------------------------------------------------------------------------
__global__ void scan3_kernel(int n, int n4, int nbs) {
    __shared__ int bs[64];
    __shared__ int ts[256];
    int t = threadIdx.x;
    int i = blockIdx.x * 256 + t;

    if (t < 64) bs[t] = (t < nbs) ? g_bsum[t] : 0;
    __syncthreads();
#pragma unroll
    for (int d = 1; d < 64; d <<= 1) {
        int v = (t < 64 && t >= d) ? bs[t - d] : 0;
        __syncthreads();
        if (t < 64) bs[t] += v;
        __syncthreads();
    }
    int base  = (blockIdx.x == 0) ? 0 : bs[blockIdx.x - 1];
    int total = bs[nbs - 1];

    int4 v = (i < n4) ? ((const int4*)g_cnt)[i] : make_int4(0, 0, 0, 0);
    int tot = v.x + v.y + v.z + v.w;
    ts[t] = tot;
    __syncthreads();
#pragma unroll
    for (int d = 1; d < 256; d <<= 1) {
        int x = (t >= d) ? ts[t - d] : 0;
        __syncthreads();
        ts[t] += x;
        __syncthreads();
    }
    if (i < n4) {
        int o0 = base + ts[t] - tot;
        int o1 = o0 + v.x, o2 = o1 + v.y, o3 = o2 + v.z;
        int4 offs = make_int4(o0, o1, o2, o3);
        ((int4*)g_off)[i] = offs;
        ((int4*)g_cnt)[i] = offs;   // cursors
    }
    if (blockIdx.x == 0 && t == 0) g_off[n] = total;
}

// ---------------------------------------------------------------------------
__global__ void fill_kernel(const void* __restrict__ ei, int e, int n) {
    int i = blockIdx.x * blockDim.x + threadIdx.x;
    if (i >= e) return;
    int r, c;
    load_edge(ei, e, i, r, c);
    if ((unsigned)r >= (unsigned)n || (unsigned)c >= (unsigned)n) return;
    int pos = atomicAdd(&g_cnt[r], 1);
    g_cols[pos] = c;
}

// ---------------------------------------------------------------------------
// Aggregate: warp per row, fp16 gathers (256B/row), fp32 accumulate.
// ---------------------------------------------------------------------------
__global__ void aggr_kernel(int n) {
    int w    = (blockIdx.x * blockDim.x + threadIdx.x) >> 5;
    int lane = threadIdx.x & 31;
    if (w >= n) return;

    int beg = g_off[w], end = g_off[w + 1];
    float4 acc = make_float4(0.f, 0.f, 0.f, 0.f);
    int j = beg;
    for (; j + 4 <= end; j += 4) {
        int c0 = g_cols[j], c1 = g_cols[j + 1], c2 = g_cols[j + 2], c3 = g_cols[j + 3];
        uint2 u0 = g_nbh[c0 * 32 + lane];
        uint2 u1 = g_nbh[c1 * 32 + lane];
        uint2 u2 = g_nbh[c2 * 32 + lane];
        uint2 u3 = g_nbh[c3 * 32 + lane];
#pragma unroll
        for (int q = 0; q < 4; ++q) {
            uint2 u = (q == 0) ? u0 : (q == 1) ? u1 : (q == 2) ? u2 : u3;
            float2 a = __half22float2(*(__half2*)&u.x);
            float2 b = __half22float2(*(__half2*)&u.y);
            acc.x += a.x; acc.y += a.y; acc.z += b.x; acc.w += b.y;
        }
    }
    for (; j < end; ++j) {
        int c = g_cols[j];
        uint2 u = g_nbh[c * 32 + lane];
        float2 a = __half22float2(*(__half2*)&u.x);
        float2 b = __half22float2(*(__half2*)&u.y);
        acc.x += a.x; acc.y += a.y; acc.z += b.x; acc.w += b.y;
    }
    g_aggr[w * 32 + lane] = acc;
}

// ---------------------------------------------------------------------------
// Fused GEMM + epilogue:  out = relu( x@W1 + aggr@W2 + s*v3 )
// Persistent: 296 blocks grid-stride over 128-row tiles. 256 thr.
// Per thread: 16 rows x 4 cols = 64 acc (8 f32x2 row-pairs x 4 cols).
// Smem: W2 full (64KB, loaded once) + As 64-k chunk [64][128] (32KB).
// ---------------------------------------------------------------------------
__global__ void __launch_bounds__(256)
gemm_fused_kernel(const float* __restrict__ x,
                  const float* __restrict__ W1,
                  const float* __restrict__ W2,
                  float* __restrict__ out, int n, int ntiles) {
    extern __shared__ float sm[];
    float* Bs = sm;            // [128][128] = W2
    float* As = sm + H * H;    // [64][128]  chunk, k-major

    const int t = threadIdx.x;
    const int w = t >> 5;
    const int l = t & 31;
    const int r0 = w * 16;     // 16 rows per warp
    const int c0 = l * 4;      // 4 cols per lane

    // W2 -> smem once
    for (int i = t; i < H * H / 4; i += 256)
        ((float4*)Bs)[i] = ((const float4*)W2)[i];

    float4 v3v = g_v3[l];
    float4 wk[8];
#pragma unroll
    for (int k = 0; k < 8; ++k) wk[k] = ((const float4*)W1)[k * 32 + l];

    for (int tile = blockIdx.x; tile < ntiles; tile += GEMM_BLOCKS) {
        const int rbase = tile * 128;

        unsigned long long acc[8][4];
#pragma unroll
        for (int p = 0; p < 8; ++p)
#pragma unroll
            for (int c = 0; c < 4; ++c) acc[p][c] = 0ULL;

#pragma unroll
        for (int chunk = 0; chunk < 2; ++chunk) {
            __syncthreads();   // As free (and Bs stores visible on first pass)
            for (int i = t; i < 2048; i += 256) {
                int row = i >> 4;      // 0..127
                int kqi = i & 15;      // float4 index within chunk
                int r = rbase + row;
                float4 v = (r < n) ? g_aggr[r * 32 + chunk * 16 + kqi]
                                   : make_float4(0.f, 0.f, 0.f, 0.f);
                As[(4 * kqi + 0) * 128 + row] = v.x;
                As[(4 * kqi + 1) * 128 + row] = v.y;
                As[(4 * kqi + 2) * 128 + row] = v.z;
                As[(4 * kqi + 3) * 128 + row] = v.w;
            }
            __syncthreads();

#pragma unroll 4
            for (int k = 0; k < 64; ++k) {
                const float4 b = *(const float4*)&Bs[(chunk * 64 + k) * H + c0];
                unsigned long long bp0 = pack2(b.x), bp1 = pack2(b.y);
                unsigned long long bp2 = pack2(b.z), bp3 = pack2(b.w);
                const unsigned long long* ap =
                    (const unsigned long long*)&As[k * 128 + r0];  // 8 pairs, warp-uniform
#pragma unroll
                for (int p = 0; p < 8; ++p) {
                    unsigned long long a = ap[p];
                    ffma2(acc[p][0], a, bp0);
                    ffma2(acc[p][1], a, bp1);
                    ffma2(acc[p][2], a, bp2);
                    ffma2(acc[p][3], a, bp3);
                }
            }
        }

        // epilogue: + x@W1 + s*v3, relu, store
#pragma unroll
        for (int p = 0; p < 8; ++p) {
            float lo[4], hi[4];
#pragma unroll
            for (int c = 0; c < 4; ++c) unpack2(acc[p][c], lo[c], hi[c]);
#pragma unroll
            for (int half = 0; half < 2; ++half) {
                int r = rbase + r0 + 2 * p + half;
                if (r >= n) continue;
                float4 o;
                if (half == 0) { o.x = lo[0]; o.y = lo[1]; o.z = lo[2]; o.w = lo[3]; }
                else           { o.x = hi[0]; o.y = hi[1]; o.z = hi[2]; o.w = hi[3]; }
                float s = g_s[r];
                o.x += s * v3v.x; o.y += s * v3v.y; o.z += s * v3v.z; o.w += s * v3v.w;

                float4 xv0 = ((const float4*)x)[r * 2];
                float4 xv1 = ((const float4*)x)[r * 2 + 1];
                float xk[8] = {xv0.x, xv0.y, xv0.z, xv0.w, xv1.x, xv1.y, xv1.z, xv1.w};
#pragma unroll
                for (int k = 0; k < 8; ++k) {
                    o.x += xk[k] * wk[k].x;
                    o.y += xk[k] * wk[k].y;
                    o.z += xk[k] * wk[k].z;
                    o.w += xk[k] * wk[k].w;
                }
                o.x = o.x > 0.f ? o.x : 0.f;
                o.y = o.y > 0.f ? o.y : 0.f;
                o.z = o.z > 0.f ? o.z : 0.f;
                o.w = o.w > 0.f ? o.w : 0.f;
                ((float4*)out)[r * 32 + l] = o;
            }
        }
    }
}

// ---------------------------------------------------------------------------
extern "C" void kernel_launch(void* const* d_in, const int* in_sizes, int n_in,
                              void* d_out, int out_size) {
    const float* x   = (const float*)d_in[0];
    const void*  ei  = d_in[1];                 // int32 or int64 (device-detected)
    const float* ea  = (const float*)d_in[2];
    const float* nb  = (const float*)d_in[3];
    const float* W1  = (const float*)d_in[4];
    const float* W2  = (const float*)d_in[5];
    const float* W3  = (const float*)d_in[6];
    const float* W4  = (const float*)d_in[7];
    float* out = (float*)d_out;

    const int n   = in_sizes[0] / 8;   // 50000
    const int e   = in_sizes[2];       // 800000
    const int n4  = (n + 3) / 4;       // 12500
    const int nbs = (n4 + 255) / 256;  // 49 scan chunks
    const int ntiles = (n + 127) / 128;

    const int smem = (H * H + 64 * H) * sizeof(float);  // 96 KB
    cudaFuncSetAttribute(gemm_fused_kernel,
                         cudaFuncAttributeMaxDynamicSharedMemorySize, smem);

    prep_kernel<<<(n * 32 + 255) / 256, 256>>>(nb, W4, W3, n);
    hist_kernel<<<(e + 255) / 256, 256>>>(ei, ea, e, n);
    scan1_kernel<<<nbs, 256>>>(n4);
    scan3_kernel<<<nbs, 256>>>(n, n4, nbs);
    fill_kernel<<<(e + 255) / 256, 256>>>(ei, e, n);
    aggr_kernel<<<(n * 32 + 255) / 256, 256>>>(n);
    gemm_fused_kernel<<<GEMM_BLOCKS, 256, smem>>>(x, W1, W2, out, n, ntiles);
}

// round 9
// speedup vs baseline: 1.4556x; 1.3449x over previous
#include <cuda_runtime.h>
#include <cuda_fp16.h>
#include <cstdint>

#define NMAX 50000
#define EMAX 800000
#define H 128

// ---------------- scratch (__device__ globals) ------------------------------
__device__ float4 g_aggr[NMAX * (H / 4)];  // segment-sum of nb rows (fp32)
__device__ uint2  g_nbh[NMAX * 32];        // node_embedding as fp16 (256B/row)
__device__ float  g_s[NMAX];               // per-node sum of edge_attr
__device__ float4 g_v3[H / 4];             // relu(W4) @ W3
__device__ int    g_cnt[NMAX];             // degree counts -> fill cursors
__device__ int    g_off[NMAX + 1];         // CSR row offsets
__device__ int    g_bsum[64];              // per-chunk sums for scan (49 used)
__device__ int    g_cols[EMAX];            // CSR column indices

// ---------------------------------------------------------------------------
__device__ __forceinline__ unsigned f2tf32(float f) {
    unsigned u;
    asm("cvt.rna.tf32.f32 %0, %1;" : "=r"(u) : "f"(f));
    return u;
}

__device__ __forceinline__ void mma_tf32(float* c, const unsigned* a,
                                         const unsigned* b) {
    asm volatile(
        "mma.sync.aligned.m16n8k8.row.col.f32.tf32.tf32.f32 "
        "{%0,%1,%2,%3}, {%4,%5,%6,%7}, {%8,%9}, {%0,%1,%2,%3};"
        : "+f"(c[0]), "+f"(c[1]), "+f"(c[2]), "+f"(c[3])
        : "r"(a[0]), "r"(a[1]), "r"(a[2]), "r"(a[3]), "r"(b[0]), "r"(b[1]));
}

__device__ __forceinline__ void load_edge(const void* __restrict__ ei, int e,
                                          int idx, int& r, int& c) {
    const int* p32 = (const int*)ei;
    bool is64 = (p32[1] | p32[3] | p32[5] | p32[7]) == 0;  // int64 => odd words 0
    if (is64) {
        const long long* p64 = (const long long*)ei;
        r = (int)p64[idx];
        c = (int)p64[e + idx];
    } else {
        r = p32[idx];
        c = p32[e + idx];
    }
}

// ---------------------------------------------------------------------------
// Prep: zero cnt/s, convert nb -> fp16 table, v3 = relu(W4)@W3 (block 0).
// ---------------------------------------------------------------------------
__global__ void prep_kernel(const float* __restrict__ nb,
                            const float* __restrict__ W4,
                            const float* __restrict__ W3, int n) {
    int i = blockIdx.x * blockDim.x + threadIdx.x;
    if (i < n) { g_cnt[i] = 0; g_s[i] = 0.f; }
    if (i < n * 32) {
        float4 v = ((const float4*)nb)[i];
        __half2 h0 = __floats2half2_rn(v.x, v.y);
        __half2 h1 = __floats2half2_rn(v.z, v.w);
        uint2 u;
        u.x = *(unsigned*)&h0;
        u.y = *(unsigned*)&h1;
        g_nbh[i] = u;
    }
    if (blockIdx.x == 0 && threadIdx.x < H) {
        int j = threadIdx.x;
        float acc = 0.f;
#pragma unroll 8
        for (int c = 0; c < H; ++c) {
            float w = W4[c];
            w = w > 0.f ? w : 0.f;
            acc += w * W3[c * H + j];
        }
        ((float*)g_v3)[j] = acc;
    }
}

// ---------------------------------------------------------------------------
__global__ void hist_kernel(const void* __restrict__ ei,
                            const float* __restrict__ ea, int e, int n) {
    int i = blockIdx.x * blockDim.x + threadIdx.x;
    if (i >= e) return;
    int r, c;
    load_edge(ei, e, i, r, c);
    if ((unsigned)r < (unsigned)n) {
        atomicAdd(&g_cnt[r], 1);
        atomicAdd(&g_s[r], ea[i]);
    }
}

// ---------------------------------------------------------------------------
__global__ void scan1_kernel(int n4) {
    __shared__ int ws[8];
    int t = threadIdx.x;
    int i = blockIdx.x * 256 + t;
    int4 v = (i < n4) ? ((const int4*)g_cnt)[i] : make_int4(0, 0, 0, 0);
    int s = v.x + v.y + v.z + v.w;
#pragma unroll
    for (int o = 16; o > 0; o >>= 1) s += __shfl_down_sync(0xffffffffu, s, o);
    if ((t & 31) == 0) ws[t >> 5] = s;
    __syncthreads();
    if (t == 0) {
        int a = 0;
#pragma unroll
        for (int k = 0; k < 8; ++k) a += ws[k];
        g_bsum[blockIdx.x] = a;
    }
}

// ---------------------------------------------------------------------------
__global__ void scan3_kernel(int n, int n4, int nbs) {
    __shared__ int bs[64];
    __shared__ int ts[256];
    int t = threadIdx.x;
    int i = blockIdx.x * 256 + t;

    if (t < 64) bs[t] = (t < nbs) ? g_bsum[t] : 0;
    __syncthreads();
#pragma unroll
    for (int d = 1; d < 64; d <<= 1) {
        int v = (t < 64 && t >= d) ? bs[t - d] : 0;
        __syncthreads();
        if (t < 64) bs[t] += v;
        __syncthreads();
    }
    int base  = (blockIdx.x == 0) ? 0 : bs[blockIdx.x - 1];
    int total = bs[nbs - 1];

    int4 v = (i < n4) ? ((const int4*)g_cnt)[i] : make_int4(0, 0, 0, 0);
    int tot = v.x + v.y + v.z + v.w;
    ts[t] = tot;
    __syncthreads();
#pragma unroll
    for (int d = 1; d < 256; d <<= 1) {
        int x = (t >= d) ? ts[t - d] : 0;
        __syncthreads();
        ts[t] += x;
        __syncthreads();
    }
    if (i < n4) {
        int o0 = base + ts[t] - tot;
        int o1 = o0 + v.x, o2 = o1 + v.y, o3 = o2 + v.z;
        int4 offs = make_int4(o0, o1, o2, o3);
        ((int4*)g_off)[i] = offs;
        ((int4*)g_cnt)[i] = offs;   // cursors
    }
    if (blockIdx.x == 0 && t == 0) g_off[n] = total;
}

// ---------------------------------------------------------------------------
__global__ void fill_kernel(const void* __restrict__ ei, int e, int n) {
    int i = blockIdx.x * blockDim.x + threadIdx.x;
    if (i >= e) return;
    int r, c;
    load_edge(ei, e, i, r, c);
    if ((unsigned)r >= (unsigned)n || (unsigned)c >= (unsigned)n) return;
    int pos = atomicAdd(&g_cnt[r], 1);
    g_cols[pos] = c;
}

// ---------------------------------------------------------------------------
// Aggregate: warp per row, fp16 gathers (256B/row), fp32 accumulate.
// ---------------------------------------------------------------------------
__global__ void aggr_kernel(int n) {
    int w    = (blockIdx.x * blockDim.x + threadIdx.x) >> 5;
    int lane = threadIdx.x & 31;
    if (w >= n) return;

    int beg = g_off[w], end = g_off[w + 1];
    float4 acc = make_float4(0.f, 0.f, 0.f, 0.f);
    int j = beg;
    for (; j + 4 <= end; j += 4) {
        int c0 = g_cols[j], c1 = g_cols[j + 1], c2 = g_cols[j + 2], c3 = g_cols[j + 3];
        uint2 u0 = g_nbh[c0 * 32 + lane];
        uint2 u1 = g_nbh[c1 * 32 + lane];
        uint2 u2 = g_nbh[c2 * 32 + lane];
        uint2 u3 = g_nbh[c3 * 32 + lane];
#pragma unroll
        for (int q = 0; q < 4; ++q) {
            uint2 u = (q == 0) ? u0 : (q == 1) ? u1 : (q == 2) ? u2 : u3;
            float2 a = __half22float2(*(__half2*)&u.x);
            float2 b = __half22float2(*(__half2*)&u.y);
            acc.x += a.x; acc.y += a.y; acc.z += b.x; acc.w += b.y;
        }
    }
    for (; j < end; ++j) {
        int c = g_cols[j];
        uint2 u = g_nbh[c * 32 + lane];
        float2 a = __half22float2(*(__half2*)&u.x);
        float2 b = __half22float2(*(__half2*)&u.y);
        acc.x += a.x; acc.y += a.y; acc.z += b.x; acc.w += b.y;
    }
    g_aggr[w * 32 + lane] = acc;
}

// ---------------------------------------------------------------------------
// Tensor-core GEMM (tf32 mma.sync), everything folded via K-extension:
//   A' = [aggr(128) | x(8) | s(1) | 0...]   (K = 160 in 5 chunks of 32)
//   B' = [W2 ; W1 ; v3 ; 0...]
//   out = relu(A' @ B')
// Block: 128 rows x 128 cols, 256 thr = 8 warps (4M x 2N), warp = 32x64.
// Smem: As[128][36] (pad->conflict-free frag loads), Bs[32][132].
// ---------------------------------------------------------------------------
#define AS_STRIDE 36
#define BS_STRIDE 132

__global__ void __launch_bounds__(256, 2)
mma_fused_kernel(const float* __restrict__ x,
                 const float* __restrict__ W1,
                 const float* __restrict__ W2,
                 float* __restrict__ out, int n) {
    __shared__ unsigned As[128 * AS_STRIDE];
    __shared__ unsigned Bs[32 * BS_STRIDE];

    const int t    = threadIdx.x;
    const int lane = t & 31;
    const int w    = t >> 5;
    const int wr0  = (w >> 1) * 32;   // warp M origin
    const int wc0  = (w & 1) * 64;    // warp N origin
    const int gid  = lane >> 2;       // groupID
    const int tig  = lane & 3;        // threadID in group
    const int rbase = blockIdx.x * 128;

    float acc[2][8][4];
#pragma unroll
    for (int mi = 0; mi < 2; ++mi)
#pragma unroll
        for (int ni = 0; ni < 8; ++ni)
#pragma unroll
            for (int q = 0; q < 4; ++q) acc[mi][ni][q] = 0.f;

    for (int chunk = 0; chunk < 5; ++chunk) {
        __syncthreads();
        if (chunk < 4) {
            // As: aggr rows, k-slice [32*chunk, +32)
            for (int i = t; i < 128 * 8; i += 256) {
                int row = i >> 3, q = i & 7;
                int r = rbase + row;
                float4 v = (r < n) ? g_aggr[r * 32 + chunk * 8 + q]
                                   : make_float4(0.f, 0.f, 0.f, 0.f);
                unsigned* p = &As[row * AS_STRIDE + 4 * q];
                p[0] = f2tf32(v.x); p[1] = f2tf32(v.y);
                p[2] = f2tf32(v.z); p[3] = f2tf32(v.w);
            }
            // Bs: W2 rows [32*chunk, +32)
            for (int i = t; i < 32 * 32; i += 256) {
                int kk = i >> 5, q = i & 31;
                float4 v = ((const float4*)W2)[(chunk * 32 + kk) * 32 + q];
                unsigned* p = &Bs[kk * BS_STRIDE + 4 * q];
                p[0] = f2tf32(v.x); p[1] = f2tf32(v.y);
                p[2] = f2tf32(v.z); p[3] = f2tf32(v.w);
            }
        } else {
            // As: [x(8) | s(1) | zeros]
            for (int i = t; i < 128 * 16; i += 256) {
                int row = i >> 4, kk = i & 15;
                int r = rbase + row;
                float v = 0.f;
                if (r < n) {
                    if (kk < 8)       v = x[r * 8 + kk];
                    else if (kk == 8) v = g_s[r];
                }
                As[row * AS_STRIDE + kk] = f2tf32(v);
            }
            // Bs: [W1(8) ; v3(1) ; zeros]
            for (int i = t; i < 16 * 128; i += 256) {
                int kk = i >> 7, col = i & 127;
                float v = 0.f;
                if (kk < 8)       v = W1[kk * H + col];
                else if (kk == 8) v = ((const float*)g_v3)[col];
                Bs[kk * BS_STRIDE + col] = f2tf32(v);
            }
        }
        __syncthreads();

        const int ksteps = (chunk < 4) ? 4 : 2;
        for (int ks = 0; ks < ksteps; ++ks) {
            const int k0 = ks * 8;
            unsigned a[2][4], b[8][2];
#pragma unroll
            for (int mi = 0; mi < 2; ++mi) {
                int row = wr0 + mi * 16 + gid;
                a[mi][0] = As[row * AS_STRIDE + k0 + tig];
                a[mi][1] = As[(row + 8) * AS_STRIDE + k0 + tig];
                a[mi][2] = As[row * AS_STRIDE + k0 + tig + 4];
                a[mi][3] = As[(row + 8) * AS_STRIDE + k0 + tig + 4];
            }
#pragma unroll
            for (int ni = 0; ni < 8; ++ni) {
                int col = wc0 + ni * 8 + gid;
                b[ni][0] = Bs[(k0 + tig) * BS_STRIDE + col];
                b[ni][1] = Bs[(k0 + tig + 4) * BS_STRIDE + col];
            }
#pragma unroll
            for (int mi = 0; mi < 2; ++mi)
#pragma unroll
                for (int ni = 0; ni < 8; ++ni)
                    mma_tf32(acc[mi][ni], a[mi], b[ni]);
        }
    }

    // epilogue: relu + store (c0,c1 = row, cols 2*tig..+1; c2,c3 = row+8)
#pragma unroll
    for (int mi = 0; mi < 2; ++mi) {
#pragma unroll
        for (int half = 0; half < 2; ++half) {
            int r = rbase + wr0 + mi * 16 + gid + half * 8;
            if (r >= n) continue;
#pragma unroll
            for (int ni = 0; ni < 8; ++ni) {
                int col = wc0 + ni * 8 + 2 * tig;
                float v0 = acc[mi][ni][half * 2 + 0];
                float v1 = acc[mi][ni][half * 2 + 1];
                v0 = v0 > 0.f ? v0 : 0.f;
                v1 = v1 > 0.f ? v1 : 0.f;
                ((float2*)out)[r * 64 + (col >> 1)] = make_float2(v0, v1);
            }
        }
    }
}

// ---------------------------------------------------------------------------
extern "C" void kernel_launch(void* const* d_in, const int* in_sizes, int n_in,
                              void* d_out, int out_size) {
    const float* x   = (const float*)d_in[0];
    const void*  ei  = d_in[1];                 // int32 or int64 (device-detected)
    const float* ea  = (const float*)d_in[2];
    const float* nb  = (const float*)d_in[3];
    const float* W1  = (const float*)d_in[4];
    const float* W2  = (const float*)d_in[5];
    const float* W3  = (const float*)d_in[6];
    const float* W4  = (const float*)d_in[7];
    float* out = (float*)d_out;

    const int n   = in_sizes[0] / 8;   // 50000
    const int e   = in_sizes[2];       // 800000
    const int n4  = (n + 3) / 4;       // 12500
    const int nbs = (n4 + 255) / 256;  // 49 scan chunks
    const int ntiles = (n + 127) / 128;

    prep_kernel<<<(n * 32 + 255) / 256, 256>>>(nb, W4, W3, n);
    hist_kernel<<<(e + 255) / 256, 256>>>(ei, ea, e, n);
    scan1_kernel<<<nbs, 256>>>(n4);
    scan3_kernel<<<nbs, 256>>>(n, n4, nbs);
    fill_kernel<<<(e + 255) / 256, 256>>>(ei, e, n);
    aggr_kernel<<<(n * 32 + 255) / 256, 256>>>(n);
    mma_fused_kernel<<<ntiles, 256>>>(x, W1, W2, out, n);
}